// round 16
// baseline (speedup 1.0000x reference)
#include <cuda_runtime.h>
#include <cstdint>

// Shapes (fixed by the problem instance)
#define B_  4
#define H_  96
#define W_  96
#define D_  96
#define NWH 12            // 96/8
#define NUM_WIN 1728      // 12*12*12
#define LEN_KEEP 691      // int(1728*0.4)
#define ELEMS_PER_OUT (B_*H_*W_*D_*32)   // 113,246,208 floats

#define NWTOT (B_ * NUM_WIN)   // 6912 windows
#define P1_ITEMS (NWTOT / 4)   // 1728 items of 4 windows (copy pass)
#define P2_ITEMS (NWTOT / 2)   // 3456 items of 2 windows (mk pass)
#define P3_ITEMS (NWTOT / 2)   // 3456 items of 2 windows (xm-zero pass)
#define GRIDB 456              // persistent blocks (~3 per SM)
#define NQUADS (NUM_WIN / 4)   // 432 float4s of noise per batch

// work-queue state (reset by the last exiting block -> replay-deterministic)
__device__ int g_c1, g_c2, g_c3, g_fin;

// stable-argsort-equivalent compare: key j vs window i's key
#define RANK_CMP(u, v, j, i) (((u) < (v)) || ((u) == (v) && (j) < (i)))

// ---------------------------------------------------------------------------
// Persistent single kernel. 456 blocks drain three GROUPED phases via global
// atomic tickets (grouping without compaction lists, no second launch):
//   pass 1: kept  -> copy x into xm     (1R:1W mix, all blocks together)
//   pass 2: all   -> mk = kept?0:1      (pure constant writes)
//   pass 3: masked-> xm = 0             (pure constant writes)
// kept is decided per item by an in-block rank scan of the batch's 1728
// noise keys (L1/L2-hot after first touch): threads 0..431 load one float4
// each, compare against the item's window keys (counts packed 16+16),
// warp shfl-reduce + one barrier + 16-way smem sum.
// Every write is a full single stream for one window (64 segments x 1KB,
// 8 float4/thread chunked 4+4 to stay under the 42-reg cap of (512,3)).
// ---------------------------------------------------------------------------
__global__ void __launch_bounds__(512, 3)
persist_kernel(const float4* __restrict__ x,
               float4* __restrict__ out_xm,
               float4* __restrict__ out_mk,
               const float* __restrict__ noise) {
    __shared__ int s_item;
    __shared__ int wredA[16], wredB[16];

    const int tid  = threadIdx.x;
    const int lane = tid & 31;
    const int wid  = tid >> 5;

    const int seg   = tid >> 3;        // 0..63 window segment
    const int lane8 = tid & 7;
    const int dh = seg >> 3;
    const int dw = seg & 7;

    // ================= PASS 1: copy kept windows (4 windows/item) ========
    for (;;) {
        if (tid == 0) s_item = atomicAdd(&g_c1, 1);
        __syncthreads();
        const int item = s_item;
        __syncthreads();                    // all read before any rewrite
        if (item >= P1_ITEMS) break;

        const int g0 = item * 4;            // 1728 % 4 == 0: no batch cross
        const int b  = g0 / NUM_WIN;
        const int i0 = g0 - b * NUM_WIN;

        const float* nb = noise + b * NUM_WIN;
        const float4 kq = __ldg((const float4*)(nb + i0));   // i0 % 4 == 0
        const unsigned v0 = __float_as_uint(kq.x);
        const unsigned v1 = __float_as_uint(kq.y);
        const unsigned v2 = __float_as_uint(kq.z);
        const unsigned v3 = __float_as_uint(kq.w);

        int cA = 0, cB = 0;
        if (tid < NQUADS) {
            const float4 q = __ldg(((const float4*)nb) + tid);
            const int j0 = 4 * tid;
            const unsigned u0 = __float_as_uint(q.x);
            const unsigned u1 = __float_as_uint(q.y);
            const unsigned u2 = __float_as_uint(q.z);
            const unsigned u3 = __float_as_uint(q.w);
            cA += RANK_CMP(u0, v0, j0 + 0, i0) + RANK_CMP(u1, v0, j0 + 1, i0)
                + RANK_CMP(u2, v0, j0 + 2, i0) + RANK_CMP(u3, v0, j0 + 3, i0);
            cA += (RANK_CMP(u0, v1, j0 + 0, i0 + 1) + RANK_CMP(u1, v1, j0 + 1, i0 + 1)
                 + RANK_CMP(u2, v1, j0 + 2, i0 + 1) + RANK_CMP(u3, v1, j0 + 3, i0 + 1)) << 16;
            cB += RANK_CMP(u0, v2, j0 + 0, i0 + 2) + RANK_CMP(u1, v2, j0 + 1, i0 + 2)
                + RANK_CMP(u2, v2, j0 + 2, i0 + 2) + RANK_CMP(u3, v2, j0 + 3, i0 + 2);
            cB += (RANK_CMP(u0, v3, j0 + 0, i0 + 3) + RANK_CMP(u1, v3, j0 + 1, i0 + 3)
                 + RANK_CMP(u2, v3, j0 + 2, i0 + 3) + RANK_CMP(u3, v3, j0 + 3, i0 + 3)) << 16;
        }
#pragma unroll
        for (int o = 16; o > 0; o >>= 1) {
            cA += __shfl_xor_sync(0xFFFFFFFFu, cA, o);
            cB += __shfl_xor_sync(0xFFFFFFFFu, cB, o);
        }
        if (lane == 0) { wredA[wid] = cA; wredB[wid] = cB; }
        __syncthreads();
        int sA = 0, sB = 0;
#pragma unroll
        for (int k = 0; k < 16; k++) { sA += wredA[k]; sB += wredB[k]; }
        const bool kept[4] = { (sA & 0xFFFF) < LEN_KEEP,
                               ((unsigned)sA >> 16) < LEN_KEEP,
                               (sB & 0xFFFF) < LEN_KEEP,
                               ((unsigned)sB >> 16) < LEN_KEEP };

#pragma unroll
        for (int k = 0; k < 4; k++) {
            if (!kept[k]) continue;
            const int i   = i0 + k;
            const int wd3 = i % NWH;
            const int r   = i / NWH;
            const int ww3 = r % NWH;
            const int wh3 = r / NWH;
            const int s0 = (((b * H_ + wh3 * 8 + dh) * W_ + ww3 * 8 + dw) * D_
                            + wd3 * 8) * 8 + lane8;
#pragma unroll
            for (int c = 0; c < 2; c++) {
                float4 vv[4];
#pragma unroll
                for (int kk = 0; kk < 4; kk++)
                    vv[kk] = __ldcs(&x[s0 + (c * 4 + kk) * 8]);
#pragma unroll
                for (int kk = 0; kk < 4; kk++)
                    __stcs(&out_xm[s0 + (c * 4 + kk) * 8], vv[kk]);
            }
        }
    }

    // ================= PASS 2: mk constants (2 windows/item) ==============
    for (;;) {
        if (tid == 0) s_item = atomicAdd(&g_c2, 1);
        __syncthreads();
        const int item = s_item;
        __syncthreads();
        if (item >= P2_ITEMS) break;

        const int g0 = item * 2;
        const int b  = g0 / NUM_WIN;
        const int i0 = g0 - b * NUM_WIN;

        const float* nb = noise + b * NUM_WIN;
        const float2 kp = __ldg((const float2*)(nb + i0));   // i0 even: 8B ok
        const unsigned v0 = __float_as_uint(kp.x);
        const unsigned v1 = __float_as_uint(kp.y);

        int cA = 0;
        if (tid < NQUADS) {
            const float4 q = __ldg(((const float4*)nb) + tid);
            const int j0 = 4 * tid;
            const unsigned u0 = __float_as_uint(q.x);
            const unsigned u1 = __float_as_uint(q.y);
            const unsigned u2 = __float_as_uint(q.z);
            const unsigned u3 = __float_as_uint(q.w);
            cA += RANK_CMP(u0, v0, j0 + 0, i0) + RANK_CMP(u1, v0, j0 + 1, i0)
                + RANK_CMP(u2, v0, j0 + 2, i0) + RANK_CMP(u3, v0, j0 + 3, i0);
            cA += (RANK_CMP(u0, v1, j0 + 0, i0 + 1) + RANK_CMP(u1, v1, j0 + 1, i0 + 1)
                 + RANK_CMP(u2, v1, j0 + 2, i0 + 1) + RANK_CMP(u3, v1, j0 + 3, i0 + 1)) << 16;
        }
#pragma unroll
        for (int o = 16; o > 0; o >>= 1)
            cA += __shfl_xor_sync(0xFFFFFFFFu, cA, o);
        if (lane == 0) wredA[wid] = cA;
        __syncthreads();
        int sA = 0;
#pragma unroll
        for (int k = 0; k < 16; k++) sA += wredA[k];
        const bool kept[2] = { (sA & 0xFFFF) < LEN_KEEP,
                               ((unsigned)sA >> 16) < LEN_KEEP };

#pragma unroll
        for (int k = 0; k < 2; k++) {
            const int i   = i0 + k;
            const int wd3 = i % NWH;
            const int r   = i / NWH;
            const int ww3 = r % NWH;
            const int wh3 = r / NWH;
            const int s0 = (((b * H_ + wh3 * 8 + dh) * W_ + ww3 * 8 + dw) * D_
                            + wd3 * 8) * 8 + lane8;
            const float fv = kept[k] ? 0.0f : 1.0f;
            const float4 c4 = make_float4(fv, fv, fv, fv);
#pragma unroll
            for (int kk = 0; kk < 8; kk++)
                __stcs(&out_mk[s0 + kk * 8], c4);
        }
    }

    // ================= PASS 3: xm zeros for masked (2 windows/item) =======
    for (;;) {
        if (tid == 0) s_item = atomicAdd(&g_c3, 1);
        __syncthreads();
        const int item = s_item;
        __syncthreads();
        if (item >= P3_ITEMS) break;

        const int g0 = item * 2;
        const int b  = g0 / NUM_WIN;
        const int i0 = g0 - b * NUM_WIN;

        const float* nb = noise + b * NUM_WIN;
        const float2 kp = __ldg((const float2*)(nb + i0));
        const unsigned v0 = __float_as_uint(kp.x);
        const unsigned v1 = __float_as_uint(kp.y);

        int cA = 0;
        if (tid < NQUADS) {
            const float4 q = __ldg(((const float4*)nb) + tid);
            const int j0 = 4 * tid;
            const unsigned u0 = __float_as_uint(q.x);
            const unsigned u1 = __float_as_uint(q.y);
            const unsigned u2 = __float_as_uint(q.z);
            const unsigned u3 = __float_as_uint(q.w);
            cA += RANK_CMP(u0, v0, j0 + 0, i0) + RANK_CMP(u1, v0, j0 + 1, i0)
                + RANK_CMP(u2, v0, j0 + 2, i0) + RANK_CMP(u3, v0, j0 + 3, i0);
            cA += (RANK_CMP(u0, v1, j0 + 0, i0 + 1) + RANK_CMP(u1, v1, j0 + 1, i0 + 1)
                 + RANK_CMP(u2, v1, j0 + 2, i0 + 1) + RANK_CMP(u3, v1, j0 + 3, i0 + 1)) << 16;
        }
#pragma unroll
        for (int o = 16; o > 0; o >>= 1)
            cA += __shfl_xor_sync(0xFFFFFFFFu, cA, o);
        if (lane == 0) wredA[wid] = cA;
        __syncthreads();
        int sA = 0;
#pragma unroll
        for (int k = 0; k < 16; k++) sA += wredA[k];
        const bool kept[2] = { (sA & 0xFFFF) < LEN_KEEP,
                               ((unsigned)sA >> 16) < LEN_KEEP };

        const float4 z = make_float4(0.f, 0.f, 0.f, 0.f);
#pragma unroll
        for (int k = 0; k < 2; k++) {
            if (kept[k]) continue;               // masked windows only
            const int i   = i0 + k;
            const int wd3 = i % NWH;
            const int r   = i / NWH;
            const int ww3 = r % NWH;
            const int wh3 = r / NWH;
            const int s0 = (((b * H_ + wh3 * 8 + dh) * W_ + ww3 * 8 + dw) * D_
                            + wd3 * 8) * 8 + lane8;
#pragma unroll
            for (int kk = 0; kk < 8; kk++)
                __stcs(&out_xm[s0 + kk * 8], z);
        }
    }

    // ---- replay-safe reset: last exiting block zeroes the queue state ----
    __syncthreads();
    if (tid == 0) {
        const int n = atomicAdd(&g_fin, 1);
        if (n == GRIDB - 1) {
            g_c1 = 0; g_c2 = 0; g_c3 = 0; g_fin = 0;
        }
    }
}

extern "C" void kernel_launch(void* const* d_in, const int* in_sizes, int n_in,
                              void* d_out, int out_size) {
    const float* x     = (const float*)d_in[0];   // [B,H,W,D,C] fp32
    const float* noise = (const float*)d_in[1];   // [B, 1728]   fp32
    float* out = (float*)d_out;                   // [x_masked | mask]

    persist_kernel<<<GRIDB, 512>>>(
        (const float4*)x,
        (float4*)out,
        (float4*)(out + (long long)ELEMS_PER_OUT),
        noise);
}